// round 3
// baseline (speedup 1.0000x reference)
#include <cuda_runtime.h>

#define N_REF 8
#define N_DIMV 16
#define BETA 1.0f
#define GAMMA 0.001f

__global__ __launch_bounds__(256) void query_ref_kernel(
    const int*   __restrict__ stim,   // [n, 9] int32 (JAX x64 disabled -> int32)
    const int*   __restrict__ cfg,    // [n]    int32
    const int*   __restrict__ grp,    // [n]    int32
    const int*   __restrict__ pres,   // [n, 9] int32
    const float* __restrict__ embed,  // [10000, 16] f32
    const float* __restrict__ attw,   // [4, 16] f32
    float*       __restrict__ out,    // [n] f32
    int n)
{
    int t = blockIdx.x * blockDim.x + threadIdx.x;
    if (t >= n) return;

    const int* s = stim + (long long)t * (N_REF + 1);
    const int* p = pres + (long long)t * (N_REF + 1);

    int g = grp[t];
    int c = cfg[t];

    // attention weights for this group (64B-aligned rows)
    const float4* wrow = (const float4*)(attw + (long long)g * N_DIMV);
    float4 w0 = __ldg(wrow + 0);
    float4 w1 = __ldg(wrow + 1);
    float4 w2 = __ldg(wrow + 2);
    float4 w3 = __ldg(wrow + 3);

    // query embedding
    int q = s[0];
    const float4* zq = (const float4*)(embed + (long long)q * N_DIMV);
    float4 q0 = __ldg(zq + 0);
    float4 q1 = __ldg(zq + 1);
    float4 q2 = __ldg(zq + 2);
    float4 q3 = __ldg(zq + 3);

    float sim[N_REF];

    #pragma unroll
    for (int j = 0; j < N_REF; j++) {
        int r = s[j + 1];
        const float4* zr = (const float4*)(embed + (long long)r * N_DIMV);
        float4 a0 = __ldg(zr + 0);
        float4 a1 = __ldg(zr + 1);
        float4 a2 = __ldg(zr + 2);
        float4 a3 = __ldg(zr + 3);

        float d;
        float dx;
        dx = q0.x - a0.x; d  = w0.x * dx * dx;
        dx = q0.y - a0.y; d += w0.y * dx * dx;
        dx = q0.z - a0.z; d += w0.z * dx * dx;
        dx = q0.w - a0.w; d += w0.w * dx * dx;
        dx = q1.x - a1.x; d += w1.x * dx * dx;
        dx = q1.y - a1.y; d += w1.y * dx * dx;
        dx = q1.z - a1.z; d += w1.z * dx * dx;
        dx = q1.w - a1.w; d += w1.w * dx * dx;
        dx = q2.x - a2.x; d += w2.x * dx * dx;
        dx = q2.y - a2.y; d += w2.y * dx * dx;
        dx = q2.z - a2.z; d += w2.z * dx * dx;
        dx = q2.w - a2.w; d += w2.w * dx * dx;
        dx = q3.x - a3.x; d += w3.x * dx * dx;
        dx = q3.y - a3.y; d += w3.y * dx * dx;
        dx = q3.z - a3.z; d += w3.z * dx * dx;
        dx = q3.w - a3.w; d += w3.w * dx * dx;

        float dist = sqrtf(d);
        float sv = __expf(-BETA * dist) + GAMMA;
        sv *= (float)p[j + 1];
        sim[j] = sv;
    }

    // reversed cumulative sums (suffix)
    float suf[N_REF];
    float acc = 0.0f;
    #pragma unroll
    for (int j = N_REF - 1; j >= 0; j--) {
        acc += sim[j];
        suf[j] = acc;
    }

    // n_select lookup: {1,2,3,1}[config]
    int nsel = (c == 1) ? 2 : ((c == 2) ? 3 : 1);

    float lik = 1.0f;
    #pragma unroll
    for (int j = 0; j < 3; j++) {   // nsel <= 3
        if (j < nsel) {
            lik *= __fdividef(sim[j], suf[j]);
        }
    }

    out[t] = lik;
}

extern "C" void kernel_launch(void* const* d_in, const int* in_sizes, int n_in,
                              void* d_out, int out_size) {
    const int*   stim  = (const int*)d_in[0];
    const int*   cfg   = (const int*)d_in[1];
    const int*   grp   = (const int*)d_in[2];
    const int*   pres  = (const int*)d_in[3];
    const float* embed = (const float*)d_in[4];
    const float* attw  = (const float*)d_in[5];
    float*       out   = (float*)d_out;

    int n = in_sizes[1];  // config_idx count == N_TRIAL
    int threads = 256;
    int blocks = (n + threads - 1) / threads;
    query_ref_kernel<<<blocks, threads>>>(stim, cfg, grp, pres, embed, attw, out, n);
}

// round 5
// speedup vs baseline: 2.1275x; 2.1275x over previous
#include <cuda_runtime.h>

#define N_REF 8
#define N_DIMV 16
#define GAMMA 0.001f

// 4 threads ("quad") per trial. Thread k owns dims 4k..4k+3.
// Embedding rows (64B, one 128B line) are loaded with ONE cooperative
// LDG.128 per row -> 1 L1 wavefront per row instead of 4.
__global__ __launch_bounds__(256) void query_ref_quad_kernel(
    const int*   __restrict__ stim,   // [n, 9] int32
    const int*   __restrict__ cfg,    // [n]    int32
    const int*   __restrict__ grp,    // [n]    int32
    const int*   __restrict__ pres,   // [n, 9] int32
    const float* __restrict__ embed,  // [10000, 16] f32
    const float* __restrict__ attw,   // [4, 16] f32
    float*       __restrict__ out,    // [n] f32
    int n)
{
    int gt = blockIdx.x * blockDim.x + threadIdx.x;
    int t = gt >> 2;          // trial
    int k = gt & 3;           // chunk within quad
    if (t >= n) return;
    unsigned mask = __activemask();

    const int* s = stim + t * (N_REF + 1);
    int g = grp[t];
    int c = cfg[t];

    // this thread's 4-dim chunk of attention weights and query embedding
    float4 w  = __ldg((const float4*)(attw  + (size_t)g * N_DIMV) + k);
    int    q  = s[0];
    float4 zq = __ldg((const float4*)(embed + (size_t)q * N_DIMV) + k);

    float dk0 = 0.0f, dk1 = 0.0f;   // full distances for refs k and k+4

    #pragma unroll
    for (int j = 0; j < N_REF; j++) {
        int r = s[j + 1];
        float4 a = __ldg((const float4*)(embed + (size_t)r * N_DIMV) + k);

        float dx, d;
        dx = zq.x - a.x; d  = w.x * dx * dx;
        dx = zq.y - a.y; d += w.y * dx * dx;
        dx = zq.z - a.z; d += w.z * dx * dx;
        dx = zq.w - a.w; d += w.w * dx * dx;

        // reduce partial distance across the quad
        d += __shfl_xor_sync(mask, d, 1);
        d += __shfl_xor_sync(mask, d, 2);

        if ((j & 3) == k) { if (j < 4) dk0 = d; else dk1 = d; }
    }

    // thread k handles sqrt/exp for refs k and k+4 (MUFU spread, not replicated)
    float sim0 = __expf(-sqrtf(dk0)) + GAMMA;
    float sim1 = __expf(-sqrtf(dk1)) + GAMMA;
    sim0 *= (float)pres[t * (N_REF + 1) + 1 + k];
    sim1 *= (float)pres[t * (N_REF + 1) + 5 + k];

    // total similarity T across all 8 refs
    float tk = sim0 + sim1;
    tk += __shfl_xor_sync(mask, tk, 1);
    tk += __shfl_xor_sync(mask, tk, 2);

    // n_select <= 3, so only sim_0, sim_1, sim_2 and suffix sums derived
    // from T are needed. sim_j (j<4) lives as sim0 of quad-lane j.
    float s1 = __shfl_sync(mask, sim0, 1, 4);
    float s2 = __shfl_sync(mask, sim0, 2, 4);

    if (k == 0) {
        int nsel = (c == 1) ? 2 : ((c == 2) ? 3 : 1);
        float suf = tk;                       // suffix[0] = total
        float lik = __fdividef(sim0, suf);
        if (nsel > 1) { suf -= sim0; lik *= __fdividef(s1, suf); }
        if (nsel > 2) { suf -= s1;   lik *= __fdividef(s2, suf); }
        out[t] = lik;
    }
}

extern "C" void kernel_launch(void* const* d_in, const int* in_sizes, int n_in,
                              void* d_out, int out_size) {
    const int*   stim  = (const int*)d_in[0];
    const int*   cfg   = (const int*)d_in[1];
    const int*   grp   = (const int*)d_in[2];
    const int*   pres  = (const int*)d_in[3];
    const float* embed = (const float*)d_in[4];
    const float* attw  = (const float*)d_in[5];
    float*       out   = (float*)d_out;

    int n = in_sizes[1];                       // N_TRIAL
    int threads = 256;
    long long total = (long long)n * 4;
    int blocks = (int)((total + threads - 1) / threads);
    query_ref_quad_kernel<<<blocks, threads>>>(stim, cfg, grp, pres, embed, attw, out, n);
}